// round 1
// baseline (speedup 1.0000x reference)
#include <cuda_runtime.h>
#include <cuda_bf16.h>
#include <cstdint>

#define NB 2
#define NS 2048
#define NT 2048
#define ND 512
#define NH 8
#define HD 64

// ---------------- scratch (device globals: no allocations allowed) ----------
__device__ float g_K[NB*NH*NS*HD];     // [b,h,s,hd]
__device__ float g_V[NB*NH*NS*HD];     // [b,h,s,hd]
__device__ float g_Q[NB*NH*NT*HD];     // [b,h,t,hd]
__device__ float g_vals[NB*NT*ND];     // [b,t,d]
__device__ float g_meanv[NB*NH*HD];    // mean of V over all S
__device__ int   g_len[4];             // src_len[0..1], tgt_len[0..1]

// ---------------- mask length extraction (dtype auto-detect) ----------------
__device__ __forceinline__ int mask_nz(const void* m, size_t idx, int mode) {
    switch (mode) {
        case 0: return ((const float*)m)[idx] != 0.0f;
        case 1: return ((const int*)m)[idx] != 0;
        case 2: return ((const unsigned char*)m)[idx] != 0;
        default: return ((const unsigned short*)m)[idx] != 0;
    }
}

__global__ void mask_lens_kernel(const void* __restrict__ mask) {
    __shared__ int s_src, s_tgt, s_mode;
    int b = blockIdx.x;
    if (threadIdx.x == 0) {
        s_src = 0; s_tgt = 0;
        unsigned int w = *(const unsigned int*)mask;  // mask[0,0,0,0..] always true
        int mode;
        if      (w == 0x3F800000u) mode = 0;  // float32 1.0
        else if (w == 0x00000001u) mode = 1;  // int32 1
        else if (w == 0x01010101u) mode = 2;  // uint8/bool 1,1,1,1
        else if (w == 0x3F803F80u) mode = 3;  // bf16 1.0,1.0
        else if ((w & 0xFF) == 1u) mode = 2;  // fallback: bytes
        else                       mode = 1;
        s_mode = mode;
    }
    __syncthreads();
    int mode = s_mode;
    size_t base = (size_t)b * NT * NS;
    int cs = 0, ct = 0;
    for (int i = threadIdx.x; i < NS; i += blockDim.x) {
        cs += mask_nz(mask, base + i, mode);                 // row t=0 (always valid)
        ct += mask_nz(mask, base + (size_t)i * NS, mode);    // col s=0 (always valid)
    }
    atomicAdd(&s_src, cs);
    atomicAdd(&s_tgt, ct);
    __syncthreads();
    if (threadIdx.x == 0) { g_len[b] = s_src; g_len[2 + b] = s_tgt; }
}

// ---------------- generic 64x64 tiled fp32 GEMM, M=4096, K=512 --------------
// mode 0: kv projection (N=1024), epilogue scatters to g_K/g_V
// mode 1: q  projection (N=512),  epilogue scatters to g_Q
// mode 2: o  projection (N=512),  A = g_vals, writes C (d_out)
__global__ void gemm64(const float* __restrict__ A, const float* __restrict__ W,
                       const float* __restrict__ bias, float* __restrict__ C,
                       int N, int mode) {
    __shared__ __align__(16) float Ast[16 * 68];  // [k][m] transposed
    __shared__ __align__(16) float Bs[16 * 68];   // [k][n]
    int tid = threadIdx.x;
    int tx = tid & 15, ty = tid >> 4;
    int m0 = blockIdx.y * 64, n0 = blockIdx.x * 64;
    const float* Ap = (mode == 2) ? g_vals : A;

    float acc[4][4] = {};
    int la_m = tid >> 2;          // 0..63
    int la_k = (tid & 3) << 2;    // 0,4,8,12
    int lb_k = tid >> 4;          // 0..15
    int lb_n = (tid & 15) << 2;   // 0..60

    for (int k0 = 0; k0 < 512; k0 += 16) {
        float4 av = *(const float4*)(Ap + (size_t)(m0 + la_m) * 512 + k0 + la_k);
        float4 bv = *(const float4*)(W + (size_t)(k0 + lb_k) * N + n0 + lb_n);
        Ast[(la_k + 0) * 68 + la_m] = av.x;
        Ast[(la_k + 1) * 68 + la_m] = av.y;
        Ast[(la_k + 2) * 68 + la_m] = av.z;
        Ast[(la_k + 3) * 68 + la_m] = av.w;
        *(float4*)(Bs + lb_k * 68 + lb_n) = bv;
        __syncthreads();
#pragma unroll
        for (int k = 0; k < 16; k++) {
            float4 a4 = *(const float4*)(Ast + k * 68 + (ty << 2));
            float4 b4 = *(const float4*)(Bs + k * 68 + (tx << 2));
            float a[4] = {a4.x, a4.y, a4.z, a4.w};
            float b[4] = {b4.x, b4.y, b4.z, b4.w};
#pragma unroll
            for (int i = 0; i < 4; i++)
#pragma unroll
                for (int j = 0; j < 4; j++)
                    acc[i][j] = fmaf(a[i], b[j], acc[i][j]);
        }
        __syncthreads();
    }

#pragma unroll
    for (int i = 0; i < 4; i++) {
        int m = m0 + (ty << 2) + i;
#pragma unroll
        for (int j = 0; j < 4; j++) {
            int n = n0 + (tx << 2) + j;
            float v = acc[i][j] + bias[n];
            if (mode == 0) {
                int b = m >> 11, s = m & 2047;
                int h = n >> 7, c = n & 127;
                size_t base = (((size_t)(b * NH + h)) * NS + s) * HD;
                if (c < HD) g_K[base + c] = v;
                else        g_V[base + c - HD] = v;
            } else if (mode == 1) {
                int b = m >> 11, t = m & 2047;
                int h = n >> 6, c = n & 63;
                g_Q[(((size_t)(b * NH + h)) * NT + t) * HD + c] = v;
            } else {
                C[(size_t)m * 512 + n] = v;
            }
        }
    }
}

// ---------------- mean of V over all S, per (b,h) ----------------------------
__global__ void meanv_kernel() {
    __shared__ float red[256];
    int bh = blockIdx.x;
    int c = threadIdx.x & 63;
    int chunk = threadIdx.x >> 6;  // 0..3
    const float* Vp = g_V + (size_t)bh * NS * HD;
    float s = 0.f;
    for (int i = chunk * 512; i < (chunk + 1) * 512; i++) s += Vp[(size_t)i * HD + c];
    red[threadIdx.x] = s;
    __syncthreads();
    if (chunk == 0)
        g_meanv[bh * HD + c] =
            (red[c] + red[c + 64] + red[c + 128] + red[c + 192]) * (1.0f / 2048.0f);
}

// ---------------- flash attention, 64 t-rows per block -----------------------
// grid (T/64, H, B), 256 threads. Dynamic smem: Qt/KV/Pt 64x68 + stats.
__global__ void attn_kernel() {
    extern __shared__ float sm[];
    float* Qt  = sm;                 // [k][t] transposed, pad 68
    float* KV  = sm + 64 * 68;       // K as [k][s] transposed, then V as [s][c]
    float* Pt  = sm + 2 * 64 * 68;   // scores/probs as [s][t] transposed
    float* m_s = sm + 3 * 64 * 68;   // 64
    float* l_s = m_s + 64;           // 64
    float* al_s = l_s + 64;          // 64

    int b = blockIdx.z, h = blockIdx.y;
    int t0 = blockIdx.x * 64;
    int tid = threadIdx.x;
    int tx = tid & 15, ty = tid >> 4;
    int warp = tid >> 5, lane = tid & 31;
    int src_len = g_len[b];
    int tgt_len = g_len[2 + b];
    size_t bh = (size_t)(b * NH + h);

    // Fully-invalid t-tile: reference softmaxes uniform(-1e9) over ALL s => mean(V).
    if (t0 >= tgt_len) {
#pragma unroll
        for (int i = 0; i < 4; i++) {
            int tg = t0 + (ty << 2) + i;
#pragma unroll
            for (int j = 0; j < 4; j++) {
                int c = (tx << 2) + j;
                g_vals[((size_t)b * NT + tg) * ND + h * HD + c] = g_meanv[bh * HD + c];
            }
        }
        return;
    }

    const float* Qg = g_Q + bh * NT * HD;
    const float* Kg = g_K + bh * NS * HD;
    const float* Vg = g_V + bh * NS * HD;

    if (tid < 64) { m_s[tid] = -1e30f; l_s[tid] = 0.f; }

    // load Q tile transposed
#pragma unroll
    for (int u = 0; u < 4; u++) {
        int lin = tid + u * 256;
        int r = lin >> 4;
        int k4 = (lin & 15) << 2;
        float4 v = *(const float4*)(Qg + (size_t)(t0 + r) * HD + k4);
        Qt[(k4 + 0) * 68 + r] = v.x;
        Qt[(k4 + 1) * 68 + r] = v.y;
        Qt[(k4 + 2) * 68 + r] = v.z;
        Qt[(k4 + 3) * 68 + r] = v.w;
    }

    float acc[4][4] = {};
    int n_tiles = (src_len + 63) >> 6;

    for (int st = 0; st < n_tiles; st++) {
        int s0 = st << 6;
        // load K tile transposed into KV
#pragma unroll
        for (int u = 0; u < 4; u++) {
            int lin = tid + u * 256;
            int r = lin >> 4;
            int k4 = (lin & 15) << 2;
            float4 v = *(const float4*)(Kg + (size_t)(s0 + r) * HD + k4);
            KV[(k4 + 0) * 68 + r] = v.x;
            KV[(k4 + 1) * 68 + r] = v.y;
            KV[(k4 + 2) * 68 + r] = v.z;
            KV[(k4 + 3) * 68 + r] = v.w;
        }
        __syncthreads();  // also covers Qt load + stats init on first iter

        // scores: sc[i][j] = sum_k Q[t0+4ty+i][k] * K[s0+4tx+j][k]
        float sc[4][4] = {};
#pragma unroll
        for (int k = 0; k < 64; k++) {
            float4 a4 = *(const float4*)(Qt + k * 68 + (ty << 2));
            float4 b4 = *(const float4*)(KV + k * 68 + (tx << 2));
            float a[4] = {a4.x, a4.y, a4.z, a4.w};
            float bb[4] = {b4.x, b4.y, b4.z, b4.w};
#pragma unroll
            for (int i = 0; i < 4; i++)
#pragma unroll
                for (int j = 0; j < 4; j++)
                    sc[i][j] = fmaf(a[i], bb[j], sc[i][j]);
        }
        // mask + scale, write transposed [s][t]
#pragma unroll
        for (int j = 0; j < 4; j++) {
            int sg = s0 + (tx << 2) + j;
            float4 out;
            float* op = (float*)&out;
#pragma unroll
            for (int i = 0; i < 4; i++) {
                int tg = t0 + (ty << 2) + i;
                bool valid = (sg < src_len) && (tg < tgt_len);
                op[i] = valid ? sc[i][j] * 0.125f : -1e9f;
            }
            *(float4*)(Pt + ((tx << 2) + j) * 68 + (ty << 2)) = out;
        }
        __syncthreads();

        // load V tile into KV (Kt no longer needed)
#pragma unroll
        for (int u = 0; u < 4; u++) {
            int lin = tid + u * 256;
            int r = lin >> 4;
            int c4 = (lin & 15) << 2;
            float4 v = *(const float4*)(Vg + (size_t)(s0 + r) * HD + c4);
            *(float4*)(KV + r * 68 + c4) = v;
        }
        // online softmax: warp w handles rows w*8..w*8+7
#pragma unroll
        for (int rr = 0; rr < 8; rr++) {
            int r = (warp << 3) + rr;
            float v0 = Pt[lane * 68 + r];
            float v1 = Pt[(lane + 32) * 68 + r];
            float mx = fmaxf(v0, v1);
#pragma unroll
            for (int o = 16; o > 0; o >>= 1) mx = fmaxf(mx, __shfl_xor_sync(0xffffffffu, mx, o));
            float m_old = m_s[r];
            float m_new = fmaxf(m_old, mx);
            float p0 = __expf(v0 - m_new);
            float p1 = __expf(v1 - m_new);
            Pt[lane * 68 + r] = p0;
            Pt[(lane + 32) * 68 + r] = p1;
            float sum = p0 + p1;
#pragma unroll
            for (int o = 16; o > 0; o >>= 1) sum += __shfl_xor_sync(0xffffffffu, sum, o);
            if (lane == 0) {
                float alpha = __expf(m_old - m_new);
                al_s[r] = alpha;
                m_s[r] = m_new;
                l_s[r] = l_s[r] * alpha + sum;
            }
        }
        __syncthreads();

        // rescale + P@V
        float al[4];
#pragma unroll
        for (int i = 0; i < 4; i++) al[i] = al_s[(ty << 2) + i];
#pragma unroll
        for (int i = 0; i < 4; i++)
#pragma unroll
            for (int j = 0; j < 4; j++) acc[i][j] *= al[i];
#pragma unroll
        for (int s = 0; s < 64; s++) {
            float4 a4 = *(const float4*)(Pt + s * 68 + (ty << 2));
            float4 b4 = *(const float4*)(KV + s * 68 + (tx << 2));
            float a[4] = {a4.x, a4.y, a4.z, a4.w};
            float bb[4] = {b4.x, b4.y, b4.z, b4.w};
#pragma unroll
            for (int i = 0; i < 4; i++)
#pragma unroll
                for (int j = 0; j < 4; j++)
                    acc[i][j] = fmaf(a[i], bb[j], acc[i][j]);
        }
        __syncthreads();
    }

    // epilogue
    float linv[4];
#pragma unroll
    for (int i = 0; i < 4; i++) linv[i] = 1.0f / l_s[(ty << 2) + i];
#pragma unroll
    for (int i = 0; i < 4; i++) {
        int tg = t0 + (ty << 2) + i;
        bool tv = tg < tgt_len;
#pragma unroll
        for (int j = 0; j < 4; j++) {
            int c = (tx << 2) + j;
            float v = tv ? acc[i][j] * linv[i] : g_meanv[bh * HD + c];
            g_vals[((size_t)b * NT + tg) * ND + h * HD + c] = v;
        }
    }
}

// ---------------- launch -----------------------------------------------------
extern "C" void kernel_launch(void* const* d_in, const int* in_sizes, int n_in,
                              void* d_out, int out_size) {
    const float* x    = (const float*)d_in[0];
    const float* y    = (const float*)d_in[1];
    const void*  mask = d_in[2];
    const float* kv_w = (const float*)d_in[3];
    const float* kv_b = (const float*)d_in[4];
    const float* q_w  = (const float*)d_in[5];
    const float* q_b  = (const float*)d_in[6];
    const float* o_w  = (const float*)d_in[7];
    const float* o_b  = (const float*)d_in[8];
    float* out = (float*)d_out;

    const int attn_smem = (3 * 64 * 68 + 3 * 64) * 4;  // 52992 B
    cudaFuncSetAttribute(attn_kernel, cudaFuncAttributeMaxDynamicSharedMemorySize,
                         attn_smem);

    mask_lens_kernel<<<2, 1024>>>(mask);
    gemm64<<<dim3(16, 64), 256>>>(x, kv_w, kv_b, nullptr, 1024, 0);
    gemm64<<<dim3(8, 64), 256>>>(y, q_w, q_b, nullptr, 512, 1);
    meanv_kernel<<<16, 256>>>();
    attn_kernel<<<dim3(NT / 64, NH, NB), 256, attn_smem>>>();
    gemm64<<<dim3(8, 64), 256>>>(nullptr, o_w, o_b, out, 512, 2);
}

// round 2
// speedup vs baseline: 3.0360x; 3.0360x over previous
#include <cuda_runtime.h>
#include <cuda_bf16.h>
#include <cstdint>

#define NB 2
#define NS 2048
#define NT 2048
#define ND 512
#define NH 8
#define HD 64

// ---------------- scratch (device globals: no allocations allowed) ----------
__device__ float g_K[NB*NH*NS*HD];     // [b,h,s,hd]
__device__ float g_V[NB*NH*NS*HD];     // [b,h,s,hd]
__device__ float g_Q[NB*NH*NT*HD];     // [b,h,t,hd]
__device__ float g_vals[NB*NT*ND];     // [b,t,d]
__device__ float g_meanv[NB*NH*HD];    // mean of V over all S
__device__ float g_mvp[16*8*64];       // meanv partials
__device__ int   g_len[4];             // src_len[0..1], tgt_len[0..1]

// ---------------- tf32 helpers ----------------------------------------------
__device__ __forceinline__ uint32_t f2tf32(float f) {
    uint32_t r;
    asm("cvt.rna.tf32.f32 %0, %1;" : "=r"(r) : "f"(f));
    return r;
}

__device__ __forceinline__ void mma8(float* c, const uint32_t* a, uint32_t b0, uint32_t b1) {
    asm volatile("mma.sync.aligned.m16n8k8.row.col.f32.tf32.tf32.f32 "
                 "{%0,%1,%2,%3}, {%4,%5,%6,%7}, {%8,%9}, {%0,%1,%2,%3};\n"
                 : "+f"(c[0]), "+f"(c[1]), "+f"(c[2]), "+f"(c[3])
                 : "r"(a[0]), "r"(a[1]), "r"(a[2]), "r"(a[3]), "r"(b0), "r"(b1));
}

// ---------------- mask length extraction (dtype auto-detect) ----------------
__device__ __forceinline__ int mask_nz(const void* m, size_t idx, int mode) {
    switch (mode) {
        case 0: return ((const float*)m)[idx] != 0.0f;
        case 1: return ((const int*)m)[idx] != 0;
        case 2: return ((const unsigned char*)m)[idx] != 0;
        default: return ((const unsigned short*)m)[idx] != 0;
    }
}

__global__ void mask_lens_kernel(const void* __restrict__ mask) {
    __shared__ int s_src, s_tgt, s_mode;
    int b = blockIdx.x;
    if (threadIdx.x == 0) {
        s_src = 0; s_tgt = 0;
        unsigned int w = *(const unsigned int*)mask;  // mask[0,0,0,0..] always true
        int mode;
        if      (w == 0x3F800000u) mode = 0;
        else if (w == 0x00000001u) mode = 1;
        else if (w == 0x01010101u) mode = 2;
        else if (w == 0x3F803F80u) mode = 3;
        else if ((w & 0xFF) == 1u) mode = 2;
        else                       mode = 1;
        s_mode = mode;
    }
    __syncthreads();
    int mode = s_mode;
    size_t base = (size_t)b * NT * NS;
    int cs = 0, ct = 0;
    for (int i = threadIdx.x; i < NS; i += blockDim.x) {
        cs += mask_nz(mask, base + i, mode);
        ct += mask_nz(mask, base + (size_t)i * NS, mode);
    }
    atomicAdd(&s_src, cs);
    atomicAdd(&s_tgt, ct);
    __syncthreads();
    if (threadIdx.x == 0) { g_len[b] = s_src; g_len[2 + b] = s_tgt; }
}

// ---------------- tf32 tensor-core GEMM: M=4096, K=512 ----------------------
// Block 128x64, BK=32, 256 threads (8 warps), warp tile 32x32.
// mode 0: kv projection (N=1024) -> scatter g_K/g_V
// mode 1: q  projection (N=512)  -> scatter g_Q
// mode 2: o  projection (N=512), A=g_vals -> C
__global__ __launch_bounds__(256) void gemm_tf32(const float* __restrict__ A,
                                                 const float* __restrict__ W,
                                                 const float* __restrict__ bias,
                                                 float* __restrict__ C,
                                                 int N, int mode) {
    __shared__ uint32_t As[128 * 36];
    __shared__ uint32_t Bs[32 * 72];
    int tid = threadIdx.x, warp = tid >> 5, lane = tid & 31;
    int ln4 = lane >> 2, lm4 = lane & 3;
    int m0 = blockIdx.y * 128, n0 = blockIdx.x * 64;
    int wm = (warp >> 1) * 32, wn = (warp & 1) * 32;
    const float* Ap = (mode == 2) ? g_vals : A;

    float c[2][4][4] = {};
    int ar = tid >> 3, aq = (tid & 7) << 2;    // A fill: row ar(+32u), col aq..aq+3
    int br = tid >> 4, bq = (tid & 15) << 2;   // B fill: row br(+16u), col bq..bq+3

    for (int k0 = 0; k0 < 512; k0 += 32) {
#pragma unroll
        for (int u = 0; u < 4; u++) {
            float4 v = *(const float4*)(Ap + (size_t)(m0 + ar + u * 32) * 512 + k0 + aq);
            uint32_t* d = As + (ar + u * 32) * 36 + aq;
            d[0] = f2tf32(v.x); d[1] = f2tf32(v.y); d[2] = f2tf32(v.z); d[3] = f2tf32(v.w);
        }
#pragma unroll
        for (int u = 0; u < 2; u++) {
            float4 v = *(const float4*)(W + (size_t)(k0 + br + u * 16) * N + n0 + bq);
            uint32_t* d = Bs + (br + u * 16) * 72 + bq;
            d[0] = f2tf32(v.x); d[1] = f2tf32(v.y); d[2] = f2tf32(v.z); d[3] = f2tf32(v.w);
        }
        __syncthreads();
#pragma unroll
        for (int kk = 0; kk < 4; kk++) {
            uint32_t a[2][4];
#pragma unroll
            for (int mi = 0; mi < 2; mi++) {
                const uint32_t* p = As + (wm + mi * 16 + ln4) * 36 + kk * 8 + lm4;
                a[mi][0] = p[0]; a[mi][1] = p[8 * 36]; a[mi][2] = p[4]; a[mi][3] = p[8 * 36 + 4];
            }
#pragma unroll
            for (int ni = 0; ni < 4; ni++) {
                uint32_t b0 = Bs[(kk * 8 + lm4) * 72 + wn + ni * 8 + ln4];
                uint32_t b1 = Bs[(kk * 8 + lm4 + 4) * 72 + wn + ni * 8 + ln4];
                mma8(c[0][ni], a[0], b0, b1);
                mma8(c[1][ni], a[1], b0, b1);
            }
        }
        __syncthreads();
    }

#pragma unroll
    for (int mi = 0; mi < 2; mi++)
#pragma unroll
        for (int ni = 0; ni < 4; ni++)
#pragma unroll
            for (int j = 0; j < 4; j++) {
                int m = m0 + wm + mi * 16 + ln4 + ((j >> 1) << 3);
                int n = n0 + wn + ni * 8 + (lm4 << 1) + (j & 1);
                float v = c[mi][ni][j] + bias[n];
                if (mode == 0) {
                    int b = m >> 11, s = m & 2047;
                    int h = n >> 7, cc = n & 127;
                    size_t base = (((size_t)(b * NH + h)) * NS + s) * HD;
                    if (cc < HD) g_K[base + cc] = v;
                    else         g_V[base + cc - HD] = v;
                } else if (mode == 1) {
                    int b = m >> 11, t = m & 2047;
                    int h = n >> 6, cc = n & 63;
                    g_Q[(((size_t)(b * NH + h)) * NT + t) * HD + cc] = v;
                } else {
                    C[(size_t)m * 512 + n] = v;
                }
            }
}

// ---------------- mean of V over all S, per (b,h): two-stage -----------------
__global__ void meanv_part() {  // grid (16, 8), 256 threads
    __shared__ float red[256];
    int bh = blockIdx.x, ch = blockIdx.y;
    int c = threadIdx.x & 63, sub = threadIdx.x >> 6;
    const float* Vp = g_V + ((size_t)bh * NS + ch * 256) * HD;
    float s = 0.f;
    for (int i = sub; i < 256; i += 4) s += Vp[(size_t)i * HD + c];
    red[threadIdx.x] = s;
    __syncthreads();
    if (sub == 0)
        g_mvp[(bh * 8 + ch) * 64 + c] = red[c] + red[c + 64] + red[c + 128] + red[c + 192];
}
__global__ void meanv_reduce() {  // grid 16, 64 threads
    int bh = blockIdx.x, c = threadIdx.x;
    float s = 0.f;
    for (int ch = 0; ch < 8; ch++) s += g_mvp[(bh * 8 + ch) * 64 + c];
    g_meanv[bh * 64 + c] = s * (1.0f / 2048.0f);
}

// ---------------- flash attention, tf32 mma, 128 t-rows/block ----------------
// 4 warps, warp tile M=32 (rows warp*32..+31), N=64. K/V share one 64x72 buffer.
__global__ __launch_bounds__(128, 2) void attn_kernel() {
    extern __shared__ uint32_t sm[];
    uint32_t* Qs  = sm;                      // [128][72] tf32
    uint32_t* KVs = sm + 128 * 72;           // [64][72] tf32 (K, then V)
    uint32_t* Ps  = sm + (128 + 64) * 72;    // [128][72] tf32

    int b = blockIdx.z, h = blockIdx.y;
    int t0 = blockIdx.x * 128;
    int tid = threadIdx.x, warp = tid >> 5, lane = tid & 31;
    int ln4 = lane >> 2, lm4 = lane & 3;
    int src_len = g_len[b], tgt_len = g_len[2 + b];
    size_t bh = (size_t)(b * NH + h);
    const float* mv = g_meanv + bh * HD;

    if (t0 >= tgt_len) {  // fully-invalid tile -> mean(V) rows
        float4 mvv[16];
#pragma unroll
        for (int q = 0; q < 16; q++) mvv[q] = *(const float4*)(mv + q * 4);
        float* op = g_vals + ((size_t)b * NT + t0 + tid) * ND + h * HD;
#pragma unroll
        for (int q = 0; q < 16; q++) *(float4*)(op + q * 4) = mvv[q];
        return;
    }

    const float* Qg = g_Q + (bh * NT + t0) * HD;
    const float* Kg = g_K + bh * NS * HD;
    const float* Vg = g_V + bh * NS * HD;

    // load Q tile 128x64 (tf32)
#pragma unroll
    for (int u = 0; u < 16; u++) {
        int lin = tid + u * 128;
        int r = lin >> 4, q = (lin & 15) << 2;
        float4 v = *(const float4*)(Qg + (size_t)r * HD + q);
        uint32_t* d = Qs + r * 72 + q;
        d[0] = f2tf32(v.x); d[1] = f2tf32(v.y); d[2] = f2tf32(v.z); d[3] = f2tf32(v.w);
    }

    float o[2][8][4] = {};
    float mrow[4] = {-1e30f, -1e30f, -1e30f, -1e30f};
    float lrow[4] = {};
    float arow[4];
    int wm = warp * 32;
    int n_tiles = (src_len + 63) >> 6;
    const float SCALE = 0.125f;

    for (int st = 0; st < n_tiles; st++) {
        int s0 = st << 6;
        __syncthreads();
        // load K tile 64x64
#pragma unroll
        for (int u = 0; u < 8; u++) {
            int lin = tid + u * 128;
            int r = lin >> 4, q = (lin & 15) << 2;
            float4 v = *(const float4*)(Kg + (size_t)(s0 + r) * HD + q);
            uint32_t* d = KVs + r * 72 + q;
            d[0] = f2tf32(v.x); d[1] = f2tf32(v.y); d[2] = f2tf32(v.z); d[3] = f2tf32(v.w);
        }
        __syncthreads();

        // S = Q @ K^T  (A: Qs[t][hd], B: K^T col-major -> KVs[s][hd])
        float s_[2][8][4] = {};
#pragma unroll
        for (int kk = 0; kk < 8; kk++) {
            uint32_t a[2][4];
#pragma unroll
            for (int mi = 0; mi < 2; mi++) {
                const uint32_t* p = Qs + (wm + mi * 16 + ln4) * 72 + kk * 8 + lm4;
                a[mi][0] = p[0]; a[mi][1] = p[8 * 72]; a[mi][2] = p[4]; a[mi][3] = p[8 * 72 + 4];
            }
#pragma unroll
            for (int ni = 0; ni < 8; ni++) {
                uint32_t b0 = KVs[(ni * 8 + ln4) * 72 + kk * 8 + lm4];
                uint32_t b1 = KVs[(ni * 8 + ln4) * 72 + kk * 8 + lm4 + 4];
                mma8(s_[0][ni], a[0], b0, b1);
                mma8(s_[1][ni], a[1], b0, b1);
            }
        }

        // online softmax (rows live in quads)
#pragma unroll
        for (int mi = 0; mi < 2; mi++)
#pragma unroll
            for (int h2 = 0; h2 < 2; h2++) {
                int ri = mi * 2 + h2;
                int rloc = wm + mi * 16 + ln4 + h2 * 8;
                bool tok = (t0 + rloc) < tgt_len;
                float mx = -1e30f;
#pragma unroll
                for (int ni = 0; ni < 8; ni++)
#pragma unroll
                    for (int cc = 0; cc < 2; cc++) {
                        int sg = s0 + ni * 8 + lm4 * 2 + cc;
                        float v = s_[mi][ni][h2 * 2 + cc];
                        v = (tok && sg < src_len) ? v * SCALE : -1e9f;
                        s_[mi][ni][h2 * 2 + cc] = v;
                        mx = fmaxf(mx, v);
                    }
                mx = fmaxf(mx, __shfl_xor_sync(0xffffffffu, mx, 1));
                mx = fmaxf(mx, __shfl_xor_sync(0xffffffffu, mx, 2));
                float mo = mrow[ri], mn = fmaxf(mo, mx);
                float alpha = __expf(mo - mn);
                float sum = 0.f;
#pragma unroll
                for (int ni = 0; ni < 8; ni++)
#pragma unroll
                    for (int cc = 0; cc < 2; cc++) {
                        float p = __expf(s_[mi][ni][h2 * 2 + cc] - mn);
                        s_[mi][ni][h2 * 2 + cc] = p;
                        sum += p;
                    }
                sum += __shfl_xor_sync(0xffffffffu, sum, 1);
                sum += __shfl_xor_sync(0xffffffffu, sum, 2);
                mrow[ri] = mn;
                lrow[ri] = lrow[ri] * alpha + sum;
                arow[ri] = alpha;
                // store P row (tf32)
                uint32_t* pr = Ps + rloc * 72 + lm4 * 2;
#pragma unroll
                for (int ni = 0; ni < 8; ni++) {
                    pr[ni * 8 + 0] = f2tf32(s_[mi][ni][h2 * 2 + 0]);
                    pr[ni * 8 + 1] = f2tf32(s_[mi][ni][h2 * 2 + 1]);
                }
            }
        __syncthreads();

        // load V tile 64x64 into KVs
#pragma unroll
        for (int u = 0; u < 8; u++) {
            int lin = tid + u * 128;
            int r = lin >> 4, q = (lin & 15) << 2;
            float4 v = *(const float4*)(Vg + (size_t)(s0 + r) * HD + q);
            uint32_t* d = KVs + r * 72 + q;
            d[0] = f2tf32(v.x); d[1] = f2tf32(v.y); d[2] = f2tf32(v.z); d[3] = f2tf32(v.w);
        }
        __syncthreads();

        // rescale O by alpha
#pragma unroll
        for (int mi = 0; mi < 2; mi++)
#pragma unroll
            for (int ni = 0; ni < 8; ni++)
#pragma unroll
                for (int j = 0; j < 4; j++)
                    o[mi][ni][j] *= arow[mi * 2 + (j >> 1)];

        // O += P @ V  (A: Ps[t][s], B: V col-major -> KVs[s][hd])
#pragma unroll
        for (int kk = 0; kk < 8; kk++) {
            uint32_t a[2][4];
#pragma unroll
            for (int mi = 0; mi < 2; mi++) {
                const uint32_t* p = Ps + (wm + mi * 16 + ln4) * 72 + kk * 8 + lm4;
                a[mi][0] = p[0]; a[mi][1] = p[8 * 72]; a[mi][2] = p[4]; a[mi][3] = p[8 * 72 + 4];
            }
#pragma unroll
            for (int ni = 0; ni < 8; ni++) {
                uint32_t b0 = KVs[(kk * 8 + lm4) * 72 + ni * 8 + ln4];
                uint32_t b1 = KVs[(kk * 8 + lm4 + 4) * 72 + ni * 8 + ln4];
                mma8(o[0][ni], a[0], b0, b1);
                mma8(o[1][ni], a[1], b0, b1);
            }
        }
    }

    // epilogue
#pragma unroll
    for (int mi = 0; mi < 2; mi++)
#pragma unroll
        for (int h2 = 0; h2 < 2; h2++) {
            int ri = mi * 2 + h2;
            int rloc = wm + mi * 16 + ln4 + h2 * 8;
            int tg = t0 + rloc;
            float li = 1.0f / lrow[ri];
            float* op = g_vals + ((size_t)b * NT + tg) * ND + h * HD;
            bool tok = tg < tgt_len;
#pragma unroll
            for (int ni = 0; ni < 8; ni++) {
                int col = ni * 8 + lm4 * 2;
                float2 w;
                if (tok) w = make_float2(o[mi][ni][h2 * 2] * li, o[mi][ni][h2 * 2 + 1] * li);
                else     w = make_float2(mv[col], mv[col + 1]);
                *(float2*)(op + col) = w;
            }
        }
}

// ---------------- launch -----------------------------------------------------
extern "C" void kernel_launch(void* const* d_in, const int* in_sizes, int n_in,
                              void* d_out, int out_size) {
    const float* x    = (const float*)d_in[0];
    const float* y    = (const float*)d_in[1];
    const void*  mask = d_in[2];
    const float* kv_w = (const float*)d_in[3];
    const float* kv_b = (const float*)d_in[4];
    const float* q_w  = (const float*)d_in[5];
    const float* q_b  = (const float*)d_in[6];
    const float* o_w  = (const float*)d_in[7];
    const float* o_b  = (const float*)d_in[8];
    float* out = (float*)d_out;

    const int attn_smem = (128 * 72 + 64 * 72 + 128 * 72) * 4;  // 92160 B
    cudaFuncSetAttribute(attn_kernel, cudaFuncAttributeMaxDynamicSharedMemorySize,
                         attn_smem);

    mask_lens_kernel<<<2, 1024>>>(mask);
    gemm_tf32<<<dim3(16, 32), 256>>>(x, kv_w, kv_b, nullptr, 1024, 0);
    gemm_tf32<<<dim3(8, 32), 256>>>(y, q_w, q_b, nullptr, 512, 1);
    meanv_part<<<dim3(16, 8), 256>>>();
    meanv_reduce<<<16, 64>>>();
    attn_kernel<<<dim3(NT / 128, NH, NB), 128, attn_smem>>>();
    gemm_tf32<<<dim3(8, 32), 256>>>(nullptr, o_w, o_b, out, 512, 2);
}

// round 3
// speedup vs baseline: 3.2127x; 1.0582x over previous
#include <cuda_runtime.h>
#include <cuda_bf16.h>
#include <cstdint>

#define NB 2
#define NS 2048
#define NT 2048
#define ND 512
#define NH 8
#define HD 64

// ---------------- scratch (device globals: no allocations allowed) ----------
__device__ float g_K[NB*NH*NS*HD];     // [b,h,s,hd]
__device__ float g_V[NB*NH*NS*HD];     // [b,h,s,hd]
__device__ float g_Q[NB*NH*NT*HD];     // [b,h,t,hd]
__device__ float g_vals[NB*NT*ND];     // [b,t,d]
__device__ float g_meanv[NB*NH*HD];    // SUM of V over all S (scaled at use)
__device__ int   g_len[4];             // src_len[0..1], tgt_len[0..1]

// ---------------- ptx helpers ------------------------------------------------
__device__ __forceinline__ void cp16(void* sdst, const void* gsrc) {
    uint32_t s = (uint32_t)__cvta_generic_to_shared(sdst);
    asm volatile("cp.async.cg.shared.global [%0], [%1], 16;\n" :: "r"(s), "l"(gsrc) : "memory");
}
__device__ __forceinline__ void cp_commit() {
    asm volatile("cp.async.commit_group;\n" ::: "memory");
}
template <int N>
__device__ __forceinline__ void cp_wait() {
    asm volatile("cp.async.wait_group %0;\n" :: "n"(N) : "memory");
}
__device__ __forceinline__ float ex2(float x) {
    float y; asm("ex2.approx.f32 %0, %1;" : "=f"(y) : "f"(x)); return y;
}
// tf32 mma on raw fp32 bits (HW reads top 19 bits; truncation ok at our tolerance)
__device__ __forceinline__ void mma8f(float* c, const float* a, float b0, float b1) {
    asm volatile("mma.sync.aligned.m16n8k8.row.col.f32.tf32.tf32.f32 "
                 "{%0,%1,%2,%3}, {%4,%5,%6,%7}, {%8,%9}, {%0,%1,%2,%3};\n"
                 : "+f"(c[0]), "+f"(c[1]), "+f"(c[2]), "+f"(c[3])
                 : "r"(__float_as_uint(a[0])), "r"(__float_as_uint(a[1])),
                   "r"(__float_as_uint(a[2])), "r"(__float_as_uint(a[3])),
                   "r"(__float_as_uint(b0)),  "r"(__float_as_uint(b1)));
}

// ---------------- mask length extraction (dtype auto-detect) ----------------
__device__ __forceinline__ int mask_nz(const void* m, size_t idx, int mode) {
    switch (mode) {
        case 0: return ((const float*)m)[idx] != 0.0f;
        case 1: return ((const int*)m)[idx] != 0;
        case 2: return ((const unsigned char*)m)[idx] != 0;
        default: return ((const unsigned short*)m)[idx] != 0;
    }
}

__global__ void mask_lens_kernel(const void* __restrict__ mask) {
    __shared__ int s_src, s_tgt, s_mode;
    int b = blockIdx.x;
    // zero the meanv accumulator (graph replays reuse it)
    if (threadIdx.x < 512) g_meanv[b * 512 + threadIdx.x] = 0.0f;
    if (threadIdx.x == 0) {
        s_src = 0; s_tgt = 0;
        unsigned int w = *(const unsigned int*)mask;  // mask[0,0,0,0..] always true
        int mode;
        if      (w == 0x3F800000u) mode = 0;
        else if (w == 0x00000001u) mode = 1;
        else if (w == 0x01010101u) mode = 2;
        else if (w == 0x3F803F80u) mode = 3;
        else if ((w & 0xFF) == 1u) mode = 2;
        else                       mode = 1;
        s_mode = mode;
    }
    __syncthreads();
    int mode = s_mode;
    size_t base = (size_t)b * NT * NS;
    int cs = 0, ct = 0;
    for (int i = threadIdx.x; i < NS; i += blockDim.x) {
        cs += mask_nz(mask, base + i, mode);
        ct += mask_nz(mask, base + (size_t)i * NS, mode);
    }
    atomicAdd(&s_src, cs);
    atomicAdd(&s_tgt, ct);
    __syncthreads();
    if (threadIdx.x == 0) { g_len[b] = s_src; g_len[2 + b] = s_tgt; }
}

// ---------------- tf32 tensor-core GEMM: M=4096, K=512, cp.async 2-stage ----
// Block 128x64, BK=32, 256 threads (8 warps), warp tile 32x32.
// mode 0: kv projection (N=1024) -> scatter g_K/g_V (+ fused V-sum for meanv)
// mode 1: q  projection (N=512)  -> scatter g_Q
// mode 2: o  projection (N=512), A=g_vals -> C
__global__ __launch_bounds__(256) void gemm_tf32(const float* __restrict__ A,
                                                 const float* __restrict__ W,
                                                 const float* __restrict__ bias,
                                                 float* __restrict__ C,
                                                 int N, int mode) {
    extern __shared__ float smf[];
    float* As = smf;                 // 2 x 128 x 36
    float* Bs = smf + 2 * 128 * 36;  // 2 x 32 x 72

    int tid = threadIdx.x, warp = tid >> 5, lane = tid & 31;
    int ln4 = lane >> 2, lm4 = lane & 3;
    int m0 = blockIdx.y * 128, n0 = blockIdx.x * 64;
    int wm = (warp >> 1) * 32, wn = (warp & 1) * 32;
    const float* Ap = (mode == 2) ? g_vals : A;

    int ar = tid >> 3, ac = (tid & 7) << 2;    // A fill: 32 rows/round, 4 rounds
    int br = tid >> 4, bc = (tid & 15) << 2;   // B fill: 16 rows/round, 2 rounds

    float c[2][4][4] = {};

    // prologue: stage 0
    {
#pragma unroll
        for (int u = 0; u < 4; u++)
            cp16(As + (ar + u * 32) * 36 + ac, Ap + (size_t)(m0 + ar + u * 32) * 512 + ac);
#pragma unroll
        for (int u = 0; u < 2; u++)
            cp16(Bs + (br + u * 16) * 72 + bc, W + (size_t)(br + u * 16) * N + n0 + bc);
        cp_commit();
    }

    for (int kt = 0; kt < 16; kt++) {
        int buf = kt & 1;
        if (kt < 15) {
            int k0 = (kt + 1) * 32, nb = buf ^ 1;
#pragma unroll
            for (int u = 0; u < 4; u++)
                cp16(As + nb * 4608 + (ar + u * 32) * 36 + ac,
                     Ap + (size_t)(m0 + ar + u * 32) * 512 + k0 + ac);
#pragma unroll
            for (int u = 0; u < 2; u++)
                cp16(Bs + nb * 2304 + (br + u * 16) * 72 + bc,
                     W + (size_t)(k0 + br + u * 16) * N + n0 + bc);
            cp_commit();
            cp_wait<1>();
        } else {
            cp_wait<0>();
        }
        __syncthreads();
        const float* Ab = As + buf * 4608;
        const float* Bb = Bs + buf * 2304;
#pragma unroll
        for (int kk = 0; kk < 4; kk++) {
            float a[2][4];
#pragma unroll
            for (int mi = 0; mi < 2; mi++) {
                const float* p = Ab + (wm + mi * 16 + ln4) * 36 + kk * 8 + lm4;
                a[mi][0] = p[0]; a[mi][1] = p[8 * 36]; a[mi][2] = p[4]; a[mi][3] = p[8 * 36 + 4];
            }
#pragma unroll
            for (int ni = 0; ni < 4; ni++) {
                float b0 = Bb[(kk * 8 + lm4) * 72 + wn + ni * 8 + ln4];
                float b1 = Bb[(kk * 8 + lm4 + 4) * 72 + wn + ni * 8 + ln4];
                mma8f(c[0][ni], a[0], b0, b1);
                mma8f(c[1][ni], a[1], b0, b1);
            }
        }
        __syncthreads();
    }

    // epilogue: scatter (+ fused V column sums for mode 0, V-half blocks)
    float colsum[4][2];
#pragma unroll
    for (int ni = 0; ni < 4; ni++) { colsum[ni][0] = 0.f; colsum[ni][1] = 0.f; }

#pragma unroll
    for (int mi = 0; mi < 2; mi++)
#pragma unroll
        for (int ni = 0; ni < 4; ni++)
#pragma unroll
            for (int j = 0; j < 4; j++) {
                int m = m0 + wm + mi * 16 + ln4 + ((j >> 1) << 3);
                int n = n0 + wn + ni * 8 + (lm4 << 1) + (j & 1);
                float v = c[mi][ni][j] + bias[n];
                if (mode == 0) {
                    int b = m >> 11, s = m & 2047;
                    int h = n >> 7, cc = n & 127;
                    size_t base = (((size_t)(b * NH + h)) * NS + s) * HD;
                    if (cc < HD) g_K[base + cc] = v;
                    else { g_V[base + cc - HD] = v; colsum[ni][j & 1] += v; }
                } else if (mode == 1) {
                    int b = m >> 11, t = m & 2047;
                    int h = n >> 6, cc = n & 63;
                    g_Q[(((size_t)(b * NH + h)) * NT + t) * HD + cc] = v;
                } else {
                    C[(size_t)m * 512 + n] = v;
                }
            }

    if (mode == 0 && (blockIdx.x & 1)) {  // V-half block: reduce 128 rows -> 64 col sums
        float* sAcc = smf;  // reuse smem (all threads past final sync)
        __syncthreads();
        if (tid < 64) sAcc[tid] = 0.f;
        __syncthreads();
#pragma unroll
        for (int ni = 0; ni < 4; ni++)
#pragma unroll
            for (int jl = 0; jl < 2; jl++)
                atomicAdd(&sAcc[wn + ni * 8 + (lm4 << 1) + jl], colsum[ni][jl]);
        __syncthreads();
        if (tid < 64) {
            int b = m0 >> 11, h = blockIdx.x >> 1;
            atomicAdd(&g_meanv[(b * NH + h) * 64 + tid], sAcc[tid]);
        }
    }
}

// ---------------- flash attention, tf32 mma, cp.async pipelined --------------
// 128 t-rows/block, 256 threads (8 warps), warp tile M=16 N=64, s-tile 64.
__global__ __launch_bounds__(256) void attn_kernel() {
    extern __shared__ float smf[];
    float* Qs = smf;                 // [128][72]
    float* Kb = smf + 128 * 72;      // [64][72]
    float* Vb = Kb + 64 * 72;        // [64][72]
    float* Ps = Vb + 64 * 72;        // [128][72]

    int b = blockIdx.z, h = blockIdx.y;
    int t0 = blockIdx.x * 128;
    int tid = threadIdx.x, warp = tid >> 5, lane = tid & 31;
    int ln4 = lane >> 2, lm4 = lane & 3;
    int src_len = g_len[b], tgt_len = g_len[2 + b];
    size_t bh = (size_t)(b * NH + h);
    const float* mv = g_meanv + bh * HD;
    const float INV_S = 1.0f / 2048.0f;

    if (t0 >= tgt_len) {  // fully-invalid tile -> mean(V) rows
        float4 mvv[8];
#pragma unroll
        for (int q = 0; q < 8; q++) {
            float4 t = *(const float4*)(mv + q * 4 + (tid & 1) * 32);
            mvv[q] = make_float4(t.x * INV_S, t.y * INV_S, t.z * INV_S, t.w * INV_S);
        }
        float* op = g_vals + ((size_t)b * NT + t0 + (tid >> 1)) * ND + h * HD + (tid & 1) * 32;
#pragma unroll
        for (int q = 0; q < 8; q++) *(float4*)(op + q * 4) = mvv[q];
        return;
    }

    const float* Qg = g_Q + (bh * NT + t0) * HD;
    const float* Kg = g_K + bh * NS * HD;
    const float* Vg = g_V + bh * NS * HD;

    int fr = tid >> 4, fc = (tid & 15) << 2;

    // prologue: Q + K0 (group 0), V0 (group 1)
#pragma unroll
    for (int u = 0; u < 8; u++)
        cp16(Qs + (fr + u * 16) * 72 + fc, Qg + (size_t)(fr + u * 16) * HD + fc);
#pragma unroll
    for (int u = 0; u < 4; u++)
        cp16(Kb + (fr + u * 16) * 72 + fc, Kg + (size_t)(fr + u * 16) * HD + fc);
    cp_commit();
#pragma unroll
    for (int u = 0; u < 4; u++)
        cp16(Vb + (fr + u * 16) * 72 + fc, Vg + (size_t)(fr + u * 16) * HD + fc);
    cp_commit();

    float o[8][4] = {};
    float mrow[2] = {-1e30f, -1e30f};
    float lrow[2] = {};
    float arow[2];
    int wm = warp * 16;
    int n_tiles = (src_len + 63) >> 6;
    const float SCALE2 = 0.125f * 1.44269504f;  // /sqrt(64) * log2(e)

    for (int st = 0; st < n_tiles; st++) {
        int s0 = st << 6;
        cp_wait<1>();          // Q + K_st ready (V_st may still fly)
        __syncthreads();

        // S = Q @ K^T
        float s_[8][4] = {};
#pragma unroll
        for (int kk = 0; kk < 8; kk++) {
            float a[4];
            const float* p = Qs + (wm + ln4) * 72 + kk * 8 + lm4;
            a[0] = p[0]; a[1] = p[8 * 72]; a[2] = p[4]; a[3] = p[8 * 72 + 4];
#pragma unroll
            for (int ni = 0; ni < 8; ni++) {
                float b0 = Kb[(ni * 8 + ln4) * 72 + kk * 8 + lm4];
                float b1 = Kb[(ni * 8 + ln4) * 72 + kk * 8 + lm4 + 4];
                mma8f(s_[ni], a, b0, b1);
            }
        }

        // online softmax (base 2); rows ln4 / ln4+8 within warp tile
#pragma unroll
        for (int h2 = 0; h2 < 2; h2++) {
            int rloc = wm + ln4 + h2 * 8;
            bool tok = (t0 + rloc) < tgt_len;
            float mx = -1e30f;
#pragma unroll
            for (int ni = 0; ni < 8; ni++)
#pragma unroll
                for (int cc = 0; cc < 2; cc++) {
                    int sg = s0 + ni * 8 + lm4 * 2 + cc;
                    float v = s_[ni][h2 * 2 + cc];
                    v = (tok && sg < src_len) ? v * SCALE2 : -2e9f;
                    s_[ni][h2 * 2 + cc] = v;
                    mx = fmaxf(mx, v);
                }
            mx = fmaxf(mx, __shfl_xor_sync(0xffffffffu, mx, 1));
            mx = fmaxf(mx, __shfl_xor_sync(0xffffffffu, mx, 2));
            float mo = mrow[h2], mn = fmaxf(mo, mx);
            float alpha = ex2(mo - mn);
            float sum = 0.f;
#pragma unroll
            for (int ni = 0; ni < 8; ni++) {
                float p0 = ex2(s_[ni][h2 * 2 + 0] - mn);
                float p1 = ex2(s_[ni][h2 * 2 + 1] - mn);
                sum += p0 + p1;
                *(float2*)(Ps + rloc * 72 + ni * 8 + lm4 * 2) = make_float2(p0, p1);
            }
            sum += __shfl_xor_sync(0xffffffffu, sum, 1);
            sum += __shfl_xor_sync(0xffffffffu, sum, 2);
            mrow[h2] = mn;
            lrow[h2] = lrow[h2] * alpha + sum;
            arow[h2] = alpha;
        }
        __syncthreads();        // Ps visible; K buffer free

        if (st + 1 < n_tiles) { // prefetch K_{st+1} while softmax/PV of this tile run
            int s1 = s0 + 64;
#pragma unroll
            for (int u = 0; u < 4; u++)
                cp16(Kb + (fr + u * 16) * 72 + fc, Kg + (size_t)(s1 + fr + u * 16) * HD + fc);
            cp_commit();
            cp_wait<1>();       // V_st done (K_{st+1} pending)
        } else {
            cp_wait<0>();       // V_st done
        }
        __syncthreads();

        // rescale O, then O += P @ V
#pragma unroll
        for (int ni = 0; ni < 8; ni++)
#pragma unroll
            for (int j = 0; j < 4; j++)
                o[ni][j] *= arow[j >> 1];
#pragma unroll
        for (int kk = 0; kk < 8; kk++) {
            float a[4];
            const float* p = Ps + (wm + ln4) * 72 + kk * 8 + lm4;
            a[0] = p[0]; a[1] = p[8 * 72]; a[2] = p[4]; a[3] = p[8 * 72 + 4];
#pragma unroll
            for (int ni = 0; ni < 8; ni++) {
                float b0 = Vb[(kk * 8 + lm4) * 72 + ni * 8 + ln4];
                float b1 = Vb[(kk * 8 + lm4 + 4) * 72 + ni * 8 + ln4];
                mma8f(o[ni], a, b0, b1);
            }
        }
        __syncthreads();        // V buffer free

        if (st + 1 < n_tiles) { // prefetch V_{st+1}: overlaps next S phase
            int s1 = s0 + 64;
#pragma unroll
            for (int u = 0; u < 4; u++)
                cp16(Vb + (fr + u * 16) * 72 + fc, Vg + (size_t)(s1 + fr + u * 16) * HD + fc);
            cp_commit();
        }
    }

    // epilogue
#pragma unroll
    for (int h2 = 0; h2 < 2; h2++) {
        int rloc = wm + ln4 + h2 * 8;
        int tg = t0 + rloc;
        bool tok = tg < tgt_len;
        float li = 1.0f / lrow[h2];
        float* op = g_vals + ((size_t)b * NT + tg) * ND + h * HD;
#pragma unroll
        for (int ni = 0; ni < 8; ni++) {
            int col = ni * 8 + lm4 * 2;
            float2 w;
            if (tok) w = make_float2(o[ni][h2 * 2] * li, o[ni][h2 * 2 + 1] * li);
            else     w = make_float2(mv[col] * INV_S, mv[col + 1] * INV_S);
            *(float2*)(op + col) = w;
        }
    }
}

// ---------------- launch -----------------------------------------------------
extern "C" void kernel_launch(void* const* d_in, const int* in_sizes, int n_in,
                              void* d_out, int out_size) {
    const float* x    = (const float*)d_in[0];
    const float* y    = (const float*)d_in[1];
    const void*  mask = d_in[2];
    const float* kv_w = (const float*)d_in[3];
    const float* kv_b = (const float*)d_in[4];
    const float* q_w  = (const float*)d_in[5];
    const float* q_b  = (const float*)d_in[6];
    const float* o_w  = (const float*)d_in[7];
    const float* o_b  = (const float*)d_in[8];
    float* out = (float*)d_out;

    const int gemm_smem = (2 * 128 * 36 + 2 * 32 * 72) * 4;              // 55296
    const int attn_smem = (128 * 72 + 64 * 72 + 64 * 72 + 128 * 72) * 4; // 110592
    cudaFuncSetAttribute(gemm_tf32, cudaFuncAttributeMaxDynamicSharedMemorySize, gemm_smem);
    cudaFuncSetAttribute(attn_kernel, cudaFuncAttributeMaxDynamicSharedMemorySize, attn_smem);

    mask_lens_kernel<<<2, 1024>>>(mask);
    gemm_tf32<<<dim3(16, 32), 256, gemm_smem>>>(x, kv_w, kv_b, nullptr, 1024, 0);
    gemm_tf32<<<dim3(8, 32), 256, gemm_smem>>>(y, q_w, q_b, nullptr, 512, 1);
    attn_kernel<<<dim3(NT / 128, NH, NB), 256, attn_smem>>>();
    gemm_tf32<<<dim3(8, 32), 256, gemm_smem>>>(nullptr, o_w, o_b, out, 512, 2);
}

// round 4
// speedup vs baseline: 3.5813x; 1.1147x over previous
#include <cuda_runtime.h>
#include <cuda_bf16.h>
#include <cstdint>

#define NB 2
#define NS 2048
#define NT 2048
#define ND 512
#define NH 8
#define HD 64

// ---------------- scratch (device globals: no allocations allowed) ----------
__device__ float g_K[NB*NH*NS*HD];     // [b,h,s,hd]   (tf32-rounded)
__device__ float g_V[NB*NH*HD*NS];     // [b,h,hd,s]   TRANSPOSED (tf32-rounded)
__device__ float g_Q[NB*NH*NT*HD];     // [b,h,t,hd]   (tf32-rounded)
__device__ float g_vals[NB*NT*ND];     // [b,t,d]
__device__ float g_meanv[NB*NH*HD];    // SUM of V over all S (scaled at use)
__device__ int   g_len[4];             // src_len[0..1], tgt_len[0..1]

// ---------------- ptx helpers ------------------------------------------------
__device__ __forceinline__ void cp16(void* sdst, const void* gsrc) {
    uint32_t s = (uint32_t)__cvta_generic_to_shared(sdst);
    asm volatile("cp.async.cg.shared.global [%0], [%1], 16;\n" :: "r"(s), "l"(gsrc) : "memory");
}
__device__ __forceinline__ void cp_commit() {
    asm volatile("cp.async.commit_group;\n" ::: "memory");
}
template <int N>
__device__ __forceinline__ void cp_wait() {
    asm volatile("cp.async.wait_group %0;\n" :: "n"(N) : "memory");
}
__device__ __forceinline__ float ex2(float x) {
    float y; asm("ex2.approx.f32 %0, %1;" : "=f"(y) : "f"(x)); return y;
}
__device__ __forceinline__ uint32_t rna_bits(float f) {
    uint32_t r; asm("cvt.rna.tf32.f32 %0, %1;" : "=r"(r) : "f"(f)); return r;
}
__device__ __forceinline__ float rnaf(float f) { return __uint_as_float(rna_bits(f)); }

__device__ __forceinline__ void ldsm4(uint32_t addr, uint32_t* r) {
    asm volatile("ldmatrix.sync.aligned.m8n8.x4.shared.b16 {%0,%1,%2,%3}, [%4];"
                 : "=r"(r[0]), "=r"(r[1]), "=r"(r[2]), "=r"(r[3]) : "r"(addr));
}
__device__ __forceinline__ void mma8u(float* c, const uint32_t* a, uint32_t b0, uint32_t b1) {
    asm volatile("mma.sync.aligned.m16n8k8.row.col.f32.tf32.tf32.f32 "
                 "{%0,%1,%2,%3}, {%4,%5,%6,%7}, {%8,%9}, {%0,%1,%2,%3};\n"
                 : "+f"(c[0]), "+f"(c[1]), "+f"(c[2]), "+f"(c[3])
                 : "r"(a[0]), "r"(a[1]), "r"(a[2]), "r"(a[3]), "r"(b0), "r"(b1));
}

// ---------------- mask length extraction (dtype auto-detect) ----------------
__device__ __forceinline__ int mask_nz(const void* m, size_t idx, int mode) {
    switch (mode) {
        case 0: return ((const float*)m)[idx] != 0.0f;
        case 1: return ((const int*)m)[idx] != 0;
        case 2: return ((const unsigned char*)m)[idx] != 0;
        default: return ((const unsigned short*)m)[idx] != 0;
    }
}

__global__ void mask_lens_kernel(const void* __restrict__ mask) {
    __shared__ int s_src, s_tgt, s_mode;
    int b = blockIdx.x;
    if (threadIdx.x < 512) g_meanv[b * 512 + threadIdx.x] = 0.0f;  // graph replays
    if (threadIdx.x == 0) {
        s_src = 0; s_tgt = 0;
        unsigned int w = *(const unsigned int*)mask;  // mask[0,0,0,0..] always true
        int mode;
        if      (w == 0x3F800000u) mode = 0;
        else if (w == 0x00000001u) mode = 1;
        else if (w == 0x01010101u) mode = 2;
        else if (w == 0x3F803F80u) mode = 3;
        else if ((w & 0xFF) == 1u) mode = 2;
        else                       mode = 1;
        s_mode = mode;
    }
    __syncthreads();
    int mode = s_mode;
    size_t base = (size_t)b * NT * NS;
    int cs = 0, ct = 0;
    for (int i = threadIdx.x; i < NS; i += blockDim.x) {
        cs += mask_nz(mask, base + i, mode);
        ct += mask_nz(mask, base + (size_t)i * NS, mode);
    }
    atomicAdd(&s_src, cs);
    atomicAdd(&s_tgt, ct);
    __syncthreads();
    if (threadIdx.x == 0) { g_len[b] = s_src; g_len[2 + b] = s_tgt; }
}

// ---------------- tf32 tensor-core GEMM: M=4096, K=512, cp.async 2-stage ----
// Block 128x64, BK=32, 256 threads (8 warps), warp tile 32x32.
// RNA rounding on fragments; outputs of modes 0/1 rounded to tf32.
__global__ __launch_bounds__(256) void gemm_tf32(const float* __restrict__ A,
                                                 const float* __restrict__ W,
                                                 const float* __restrict__ bias,
                                                 float* __restrict__ C,
                                                 int N, int mode) {
    extern __shared__ float smf[];
    float* As = smf;                 // 2 x 128 x 36
    float* Bs = smf + 2 * 128 * 36;  // 2 x 32 x 72

    int tid = threadIdx.x, warp = tid >> 5, lane = tid & 31;
    int ln4 = lane >> 2, lm4 = lane & 3;
    int mat = lane >> 3, mr = lane & 7;
    int a_row = (mat & 1) * 8 + mr, a_col = (mat >> 1) * 4;  // ldmatrix A-scheme
    int m0 = blockIdx.y * 128, n0 = blockIdx.x * 64;
    int wm = (warp >> 1) * 32, wn = (warp & 1) * 32;
    const float* Ap = (mode == 2) ? g_vals : A;

    int ar = tid >> 3, ac = (tid & 7) << 2;
    int br = tid >> 4, bc = (tid & 15) << 2;

    float c[2][4][4] = {};

    // prologue: stage 0
#pragma unroll
    for (int u = 0; u < 4; u++)
        cp16(As + (ar + u * 32) * 36 + ac, Ap + (size_t)(m0 + ar + u * 32) * 512 + ac);
#pragma unroll
    for (int u = 0; u < 2; u++)
        cp16(Bs + (br + u * 16) * 72 + bc, W + (size_t)(br + u * 16) * N + n0 + bc);
    cp_commit();

    for (int kt = 0; kt < 16; kt++) {
        int buf = kt & 1;
        if (kt < 15) {
            int k0 = (kt + 1) * 32, nb = buf ^ 1;
#pragma unroll
            for (int u = 0; u < 4; u++)
                cp16(As + nb * 4608 + (ar + u * 32) * 36 + ac,
                     Ap + (size_t)(m0 + ar + u * 32) * 512 + k0 + ac);
#pragma unroll
            for (int u = 0; u < 2; u++)
                cp16(Bs + nb * 2304 + (br + u * 16) * 72 + bc,
                     W + (size_t)(k0 + br + u * 16) * N + n0 + bc);
            cp_commit();
            cp_wait<1>();
        } else {
            cp_wait<0>();
        }
        __syncthreads();
        const float* Ab = As + buf * 4608;
        const float* Bb = Bs + buf * 2304;
        uint32_t Aa0 = (uint32_t)__cvta_generic_to_shared(Ab + (wm + a_row) * 36 + a_col);
        uint32_t Aa1 = (uint32_t)__cvta_generic_to_shared(Ab + (wm + 16 + a_row) * 36 + a_col);
#pragma unroll
        for (int kk = 0; kk < 4; kk++) {
            uint32_t a[2][4];
            ldsm4(Aa0 + kk * 32, a[0]);
            ldsm4(Aa1 + kk * 32, a[1]);
#pragma unroll
            for (int mi = 0; mi < 2; mi++)
#pragma unroll
                for (int i = 0; i < 4; i++)
                    a[mi][i] = rna_bits(__uint_as_float(a[mi][i]));
#pragma unroll
            for (int ni = 0; ni < 4; ni++) {
                uint32_t b0 = rna_bits(Bb[(kk * 8 + lm4) * 72 + wn + ni * 8 + ln4]);
                uint32_t b1 = rna_bits(Bb[(kk * 8 + lm4 + 4) * 72 + wn + ni * 8 + ln4]);
                mma8u(c[0][ni], a[0], b0, b1);
                mma8u(c[1][ni], a[1], b0, b1);
            }
        }
        __syncthreads();
    }

    // epilogue: scatter (+ fused V column sums for mode 0 V-half blocks)
    float colsum[4][2];
#pragma unroll
    for (int ni = 0; ni < 4; ni++) { colsum[ni][0] = 0.f; colsum[ni][1] = 0.f; }

#pragma unroll
    for (int mi = 0; mi < 2; mi++)
#pragma unroll
        for (int ni = 0; ni < 4; ni++)
#pragma unroll
            for (int j = 0; j < 4; j++) {
                int m = m0 + wm + mi * 16 + ln4 + ((j >> 1) << 3);
                int n = n0 + wn + ni * 8 + (lm4 << 1) + (j & 1);
                float v = c[mi][ni][j] + bias[n];
                if (mode == 0) {
                    v = rnaf(v);
                    int b = m >> 11, s = m & 2047;
                    int h = n >> 7, cc = n & 127;
                    if (cc < HD)
                        g_K[(((size_t)(b * NH + h)) * NS + s) * HD + cc] = v;
                    else {
                        g_V[(((size_t)(b * NH + h)) * HD + cc - HD) * NS + s] = v;
                        colsum[ni][j & 1] += v;
                    }
                } else if (mode == 1) {
                    v = rnaf(v);
                    int b = m >> 11, t = m & 2047;
                    int h = n >> 6, cc = n & 63;
                    g_Q[(((size_t)(b * NH + h)) * NT + t) * HD + cc] = v;
                } else {
                    C[(size_t)m * 512 + n] = v;
                }
            }

    if (mode == 0 && (blockIdx.x & 1)) {
        float* sAcc = smf;
        __syncthreads();
        if (tid < 64) sAcc[tid] = 0.f;
        __syncthreads();
#pragma unroll
        for (int ni = 0; ni < 4; ni++)
#pragma unroll
            for (int jl = 0; jl < 2; jl++)
                atomicAdd(&sAcc[wn + ni * 8 + (lm4 << 1) + jl], colsum[ni][jl]);
        __syncthreads();
        if (tid < 64) {
            int b = m0 >> 11, h = blockIdx.x >> 1;
            atomicAdd(&g_meanv[(b * NH + h) * 64 + tid], sAcc[tid]);
        }
    }
}

// ---------------- flash attention: tf32 mma + ldmatrix, cp.async pipelined ---
// 128 t-rows/block, 128 threads (4 warps), warp tile M=32 N=64, s-tile 64.
__global__ __launch_bounds__(128) void attn_kernel() {
    extern __shared__ float smf[];
    float* Qs = smf;                 // [128][76]
    float* Kb = Qs + 128 * 76;       // [64][76]  rows=s, cols=hd
    float* Vt = Kb + 64 * 76;        // [64][76]  rows=hd, cols=s (transposed V)
    float* Ps = Vt + 64 * 76;        // [128][72] rows=t, cols=s

    int b = blockIdx.z, h = blockIdx.y;
    int t0 = blockIdx.x * 128;
    int tid = threadIdx.x, warp = tid >> 5, lane = tid & 31;
    int ln4 = lane >> 2, lm4 = lane & 3;
    int mat = lane >> 3, mr = lane & 7;
    int a_row = (mat & 1) * 8 + mr, a_col = (mat >> 1) * 4;  // A-scheme (Q, P)
    int b_row = (mat >> 1) * 8 + mr, b_col = (mat & 1) * 4;  // B-scheme (K, Vt)
    int src_len = g_len[b], tgt_len = g_len[2 + b];
    size_t bh = (size_t)(b * NH + h);
    const float* mv = g_meanv + bh * HD;
    const float INV_S = 1.0f / 2048.0f;

    if (t0 >= tgt_len) {  // fully-invalid tile -> mean(V) rows
        float* op = g_vals + ((size_t)b * NT + t0 + tid) * ND + h * HD;
#pragma unroll
        for (int q = 0; q < 16; q++) {
            float4 t = *(const float4*)(mv + q * 4);
            *(float4*)(op + q * 4) = make_float4(t.x * INV_S, t.y * INV_S, t.z * INV_S, t.w * INV_S);
        }
        return;
    }

    const float* Qg = g_Q + (bh * NT + t0) * HD;
    const float* Kg = g_K + bh * NS * HD;
    const float* Vg = g_V + bh * HD * NS;   // [hd][s]

    int fr = tid >> 4, fc = (tid & 15) << 2;

    // prologue: Q + K0 (group 0), V0 (group 1)
#pragma unroll
    for (int u = 0; u < 16; u++)
        cp16(Qs + (fr + u * 8) * 76 + fc, Qg + (size_t)(fr + u * 8) * HD + fc);
#pragma unroll
    for (int u = 0; u < 8; u++)
        cp16(Kb + (fr + u * 8) * 76 + fc, Kg + (size_t)(fr + u * 8) * HD + fc);
    cp_commit();
#pragma unroll
    for (int u = 0; u < 8; u++)
        cp16(Vt + (fr + u * 8) * 76 + fc, Vg + (size_t)(fr + u * 8) * NS + fc);
    cp_commit();

    int wm = warp * 32;
    uint32_t Qa0 = (uint32_t)__cvta_generic_to_shared(Qs + (wm + a_row) * 76 + a_col);
    uint32_t Qa1 = (uint32_t)__cvta_generic_to_shared(Qs + (wm + 16 + a_row) * 76 + a_col);
    uint32_t Ka  = (uint32_t)__cvta_generic_to_shared(Kb + b_row * 76 + b_col);
    uint32_t Va  = (uint32_t)__cvta_generic_to_shared(Vt + b_row * 76 + b_col);
    uint32_t Pa0 = (uint32_t)__cvta_generic_to_shared(Ps + (wm + a_row) * 72 + a_col);
    uint32_t Pa1 = (uint32_t)__cvta_generic_to_shared(Ps + (wm + 16 + a_row) * 72 + a_col);

    float o[2][8][4] = {};
    float mrow[2][2] = {{-1e30f, -1e30f}, {-1e30f, -1e30f}};
    float lrow[2][2] = {};
    float arow[2][2];
    int n_tiles = (src_len + 63) >> 6;
    const float SCALE2 = 0.125f * 1.44269504f;  // /sqrt(64) * log2(e)

    for (int st = 0; st < n_tiles; st++) {
        int s0 = st << 6;
        cp_wait<1>();          // Q + K_st ready (V_st may still fly)
        __syncthreads();

        // S = Q @ K^T  (ldmatrix all operands; data pre-rounded to tf32)
        float s_[2][8][4] = {};
#pragma unroll
        for (int kk = 0; kk < 8; kk++) {
            uint32_t aq[2][4];
            ldsm4(Qa0 + kk * 32, aq[0]);
            ldsm4(Qa1 + kk * 32, aq[1]);
#pragma unroll
            for (int n2 = 0; n2 < 4; n2++) {
                uint32_t bb[4];
                ldsm4(Ka + n2 * (16 * 76 * 4) + kk * 32, bb);
                mma8u(s_[0][n2 * 2 + 0], aq[0], bb[0], bb[1]);
                mma8u(s_[0][n2 * 2 + 1], aq[0], bb[2], bb[3]);
                mma8u(s_[1][n2 * 2 + 0], aq[1], bb[0], bb[1]);
                mma8u(s_[1][n2 * 2 + 1], aq[1], bb[2], bb[3]);
            }
        }

        // online softmax (base 2), 4 row-groups per thread
#pragma unroll
        for (int mi = 0; mi < 2; mi++)
#pragma unroll
            for (int h2 = 0; h2 < 2; h2++) {
                int rloc = wm + mi * 16 + h2 * 8 + ln4;
                bool tok = (t0 + rloc) < tgt_len;
                float mx = -1e30f;
#pragma unroll
                for (int ni = 0; ni < 8; ni++)
#pragma unroll
                    for (int cc = 0; cc < 2; cc++) {
                        int sg = s0 + ni * 8 + lm4 * 2 + cc;
                        float v = s_[mi][ni][h2 * 2 + cc];
                        v = (tok && sg < src_len) ? v * SCALE2 : -2e9f;
                        s_[mi][ni][h2 * 2 + cc] = v;
                        mx = fmaxf(mx, v);
                    }
                mx = fmaxf(mx, __shfl_xor_sync(0xffffffffu, mx, 1));
                mx = fmaxf(mx, __shfl_xor_sync(0xffffffffu, mx, 2));
                float mo = mrow[mi][h2], mn = fmaxf(mo, mx);
                float alpha = ex2(mo - mn);
                float sum = 0.f;
#pragma unroll
                for (int ni = 0; ni < 8; ni++) {
                    float p0 = rnaf(ex2(s_[mi][ni][h2 * 2 + 0] - mn));
                    float p1 = rnaf(ex2(s_[mi][ni][h2 * 2 + 1] - mn));
                    sum += p0 + p1;
                    *(float2*)(Ps + rloc * 72 + ni * 8 + lm4 * 2) = make_float2(p0, p1);
                }
                sum += __shfl_xor_sync(0xffffffffu, sum, 1);
                sum += __shfl_xor_sync(0xffffffffu, sum, 2);
                mrow[mi][h2] = mn;
                lrow[mi][h2] = lrow[mi][h2] * alpha + sum;
                arow[mi][h2] = alpha;
            }
        __syncwarp();
        __syncthreads();        // all warps done reading K; P visible

        if (st + 1 < n_tiles) { // prefetch K_{st+1}; overlaps PV
            int s1 = s0 + 64;
#pragma unroll
            for (int u = 0; u < 8; u++)
                cp16(Kb + (fr + u * 8) * 76 + fc, Kg + (size_t)(s1 + fr + u * 8) * HD + fc);
            cp_commit();
            cp_wait<1>();       // V_st done (K_{st+1} pending)
        } else {
            cp_wait<0>();
        }
        __syncthreads();

        // rescale O, then O += P @ V
#pragma unroll
        for (int mi = 0; mi < 2; mi++)
#pragma unroll
            for (int ni = 0; ni < 8; ni++)
#pragma unroll
                for (int j = 0; j < 4; j++)
                    o[mi][ni][j] *= arow[mi][j >> 1];
#pragma unroll
        for (int kk = 0; kk < 8; kk++) {
            uint32_t ap[2][4];
            ldsm4(Pa0 + kk * 32, ap[0]);
            ldsm4(Pa1 + kk * 32, ap[1]);
#pragma unroll
            for (int n2 = 0; n2 < 4; n2++) {
                uint32_t bb[4];
                ldsm4(Va + n2 * (16 * 76 * 4) + kk * 32, bb);
                mma8u(o[0][n2 * 2 + 0], ap[0], bb[0], bb[1]);
                mma8u(o[0][n2 * 2 + 1], ap[0], bb[2], bb[3]);
                mma8u(o[1][n2 * 2 + 0], ap[1], bb[0], bb[1]);
                mma8u(o[1][n2 * 2 + 1], ap[1], bb[2], bb[3]);
            }
        }
        __syncthreads();        // V buffer free

        if (st + 1 < n_tiles) { // prefetch V_{st+1}; overlaps next S phase
            int s1 = s0 + 64;
#pragma unroll
            for (int u = 0; u < 8; u++)
                cp16(Vt + (fr + u * 8) * 76 + fc, Vg + (size_t)(fr + u * 8) * NS + s1 + fc);
            cp_commit();
        }
    }

    // epilogue
#pragma unroll
    for (int mi = 0; mi < 2; mi++)
#pragma unroll
        for (int h2 = 0; h2 < 2; h2++) {
            int rloc = wm + mi * 16 + h2 * 8 + ln4;
            int tg = t0 + rloc;
            bool tok = tg < tgt_len;
            float li = 1.0f / lrow[mi][h2];
            float* op = g_vals + ((size_t)b * NT + tg) * ND + h * HD;
#pragma unroll
            for (int ni = 0; ni < 8; ni++) {
                int col = ni * 8 + lm4 * 2;
                float2 w;
                if (tok) w = make_float2(o[mi][ni][h2 * 2] * li, o[mi][ni][h2 * 2 + 1] * li);
                else     w = make_float2(mv[col] * INV_S, mv[col + 1] * INV_S);
                *(float2*)(op + col) = w;
            }
        }
}

// ---------------- launch -----------------------------------------------------
extern "C" void kernel_launch(void* const* d_in, const int* in_sizes, int n_in,
                              void* d_out, int out_size) {
    const float* x    = (const float*)d_in[0];
    const float* y    = (const float*)d_in[1];
    const void*  mask = d_in[2];
    const float* kv_w = (const float*)d_in[3];
    const float* kv_b = (const float*)d_in[4];
    const float* q_w  = (const float*)d_in[5];
    const float* q_b  = (const float*)d_in[6];
    const float* o_w  = (const float*)d_in[7];
    const float* o_b  = (const float*)d_in[8];
    float* out = (float*)d_out;

    const int gemm_smem = (2 * 128 * 36 + 2 * 32 * 72) * 4;              // 55296
    const int attn_smem = (128 * 76 + 64 * 76 + 64 * 76 + 128 * 72) * 4; // 114688
    cudaFuncSetAttribute(gemm_tf32, cudaFuncAttributeMaxDynamicSharedMemorySize, gemm_smem);
    cudaFuncSetAttribute(attn_kernel, cudaFuncAttributeMaxDynamicSharedMemorySize, attn_smem);

    mask_lens_kernel<<<2, 1024>>>(mask);
    gemm_tf32<<<dim3(16, 32), 256, gemm_smem>>>(x, kv_w, kv_b, nullptr, 1024, 0);
    gemm_tf32<<<dim3(8, 32), 256, gemm_smem>>>(y, q_w, q_b, nullptr, 512, 1);
    attn_kernel<<<dim3(NT / 128, NH, NB), 128, attn_smem>>>();
    gemm_tf32<<<dim3(8, 32), 256, gemm_smem>>>(nullptr, o_w, o_b, out, 512, 2);
}